// round 1
// baseline (speedup 1.0000x reference)
#include <cuda_runtime.h>
#include <cstdint>

// Problem shape (fixed by the dataset)
#define NB_ 8
#define T_  200
#define U_  50
#define J_  512
#define V_  500
#define NT_ (NB_*T_)   // 1600
#define NU_ (NB_*U_)   // 400
// rows of the big GEMM: NT_*U_ = 80000, divisible by 64 -> grid 1250

// Scratch for projected encoder/decoder (bias folded in)
__device__ float g_encP[NT_*J_];   // [1600][512]
__device__ float g_decP[NU_*J_];   // [400][512]

// ---------------------------------------------------------------------------
// Projection GEMM: C[m][j] = sum_k A[m][k] * W[j][k] + bias[j],  K = N = 512
// 64x64 tile, 4x4 per thread, 256 threads. Small kernels (~1 GF total).
// ---------------------------------------------------------------------------
__global__ __launch_bounds__(256) void proj_kernel(
    const float* __restrict__ A, const float* __restrict__ W,
    const float* __restrict__ bias, float* __restrict__ C, int M)
{
    __shared__ __align__(16) float As[64][17];
    __shared__ __align__(16) float Ws[64][17];

    const int tid = threadIdx.x;
    const int tx  = tid & 15;        // col group
    const int ty  = tid >> 4;        // row group
    const int m0  = blockIdx.y * 64;
    const int j0  = blockIdx.x * 64;
    const int lr  = tid >> 2;        // 0..63 : row loaded by this thread
    const int lk  = (tid & 3) * 4;   // 0,4,8,12 : k offset (float4)

    float acc[4][4];
#pragma unroll
    for (int i = 0; i < 4; i++)
#pragma unroll
        for (int j = 0; j < 4; j++) acc[i][j] = 0.f;

    for (int k0 = 0; k0 < 512; k0 += 16) {
        float4 av = make_float4(0.f, 0.f, 0.f, 0.f);
        if (m0 + lr < M)
            av = *(const float4*)(A + (size_t)(m0 + lr) * 512 + k0 + lk);
        float4 wv = *(const float4*)(W + (size_t)(j0 + lr) * 512 + k0 + lk);

        __syncthreads();
        As[lr][lk+0] = av.x; As[lr][lk+1] = av.y; As[lr][lk+2] = av.z; As[lr][lk+3] = av.w;
        Ws[lr][lk+0] = wv.x; Ws[lr][lk+1] = wv.y; Ws[lr][lk+2] = wv.z; Ws[lr][lk+3] = wv.w;
        __syncthreads();

#pragma unroll
        for (int k = 0; k < 16; k++) {
            float a[4], b[4];
#pragma unroll
            for (int i = 0; i < 4; i++) a[i] = As[ty + 16*i][k];
#pragma unroll
            for (int j = 0; j < 4; j++) b[j] = Ws[tx + 16*j][k];
#pragma unroll
            for (int i = 0; i < 4; i++)
#pragma unroll
                for (int j = 0; j < 4; j++)
                    acc[i][j] = fmaf(a[i], b[j], acc[i][j]);
        }
    }

#pragma unroll
    for (int i = 0; i < 4; i++) {
        int m = m0 + ty + 16*i;
        if (m >= M) continue;
#pragma unroll
        for (int j = 0; j < 4; j++) {
            int jj = j0 + tx + 16*j;               // < 512 always
            C[(size_t)m * 512 + jj] = acc[i][j] + bias[jj];
        }
    }
}

// ---------------------------------------------------------------------------
// Main fused kernel:
//   out[row][v] = sum_k tanh(encP[nt][k] + decP[n*U+u][k]) * Wout[v][k] + bout[v]
// row = nt*U + u, 80000 rows. Tile: 64 rows x 128 vocab cols, 256 threads,
// per-thread 4 rows x 4 f32x2 column-pairs (fma.rn.f32x2 -> full-rate fp32).
// ---------------------------------------------------------------------------
__global__ __launch_bounds__(256) void joiner_main(
    const float* __restrict__ Wout,   // [500][512]
    const float* __restrict__ bout,   // [500]
    float* __restrict__ out)          // [80000][500]
{
    __shared__ __align__(16) float As[64][17];    // act, [m][k]
    __shared__ __align__(16) float Bs[16][132];   // W,   [k][v] (pad 132)

    const int tid = threadIdx.x;
    const int tx  = tid & 15;
    const int ty  = tid >> 4;
    const long r0 = (long)blockIdx.y * 64;        // row base (grid.y = 1250, exact)
    const int v0  = blockIdx.x * 128;             // vocab base (grid.x = 4)

    const int lr = tid >> 2;                      // 0..63
    const int lk = (tid & 3) * 4;                 // 0,4,8,12

    // row this thread stages into As
    const long row = r0 + lr;                     // always < 80000
    const int nt = (int)(row / U_);
    const int u  = (int)(row - (long)nt * U_);
    const int n  = nt / T_;
    const float* encRow = g_encP + (size_t)nt * 512;
    const float* decRow = g_decP + ((size_t)n * U_ + u) * 512;

    // W rows this thread stages into Bs (two of them)
    const int vA = v0 + lr;
    const int vB = v0 + 64 + lr;
    const float* wRowA = (vA < V_) ? (Wout + (size_t)vA * 512) : nullptr;
    const float* wRowB = (vB < V_) ? (Wout + (size_t)vB * 512) : nullptr;

    unsigned long long acc[4][4];   // f32x2 accumulators: 4 rows x 4 col-pairs
#pragma unroll
    for (int i = 0; i < 4; i++)
#pragma unroll
        for (int jp = 0; jp < 4; jp++) acc[i][jp] = 0ull;

    for (int k0 = 0; k0 < 512; k0 += 16) {
        // activation fragment: tanh(enc + dec), 4 consecutive k for one row
        float4 e = *(const float4*)(encRow + k0 + lk);
        float4 d = *(const float4*)(decRow + k0 + lk);
        float4 av;
        av.x = tanhf(e.x + d.x);
        av.y = tanhf(e.y + d.y);
        av.z = tanhf(e.z + d.z);
        av.w = tanhf(e.w + d.w);

        float4 w0 = make_float4(0.f, 0.f, 0.f, 0.f);
        float4 w1 = make_float4(0.f, 0.f, 0.f, 0.f);
        if (wRowA) w0 = *(const float4*)(wRowA + k0 + lk);
        if (wRowB) w1 = *(const float4*)(wRowB + k0 + lk);

        __syncthreads();
        As[lr][lk+0] = av.x; As[lr][lk+1] = av.y; As[lr][lk+2] = av.z; As[lr][lk+3] = av.w;
        Bs[lk+0][lr] = w0.x; Bs[lk+1][lr] = w0.y; Bs[lk+2][lr] = w0.z; Bs[lk+3][lr] = w0.w;
        Bs[lk+0][64+lr] = w1.x; Bs[lk+1][64+lr] = w1.y; Bs[lk+2][64+lr] = w1.z; Bs[lk+3][64+lr] = w1.w;
        __syncthreads();

#pragma unroll
        for (int k = 0; k < 16; k++) {
            unsigned long long a2[4], b2[4];
#pragma unroll
            for (int i = 0; i < 4; i++) {
                float a = As[ty + 16*i][k];                 // broadcast across half-warp
                asm("mov.b64 %0, {%1, %1};" : "=l"(a2[i]) : "f"(a));
            }
#pragma unroll
            for (int jp = 0; jp < 4; jp++)                   // contiguous 8B/lane, conflict-free
                b2[jp] = *(const unsigned long long*)&Bs[k][32*jp + 2*tx];
#pragma unroll
            for (int i = 0; i < 4; i++)
#pragma unroll
                for (int jp = 0; jp < 4; jp++)
                    asm("fma.rn.f32x2 %0, %1, %2, %0;"
                        : "+l"(acc[i][jp]) : "l"(a2[i]), "l"(b2[jp]));
        }
    }

    // epilogue
#pragma unroll
    for (int i = 0; i < 4; i++) {
        const long rr = r0 + ty + 16*i;                      // < 80000 always
        float* orow = out + rr * (long)V_;
#pragma unroll
        for (int jp = 0; jp < 4; jp++) {
            const int v = v0 + 32*jp + 2*tx;
            float2 res = *(float2*)&acc[i][jp];              // .x = col v, .y = col v+1
            if (v < V_)     orow[v]     = res.x + bout[v];
            if (v + 1 < V_) orow[v + 1] = res.y + bout[v + 1];
        }
    }
}

// ---------------------------------------------------------------------------
extern "C" void kernel_launch(void* const* d_in, const int* in_sizes, int n_in,
                              void* d_out, int out_size)
{
    (void)in_sizes; (void)n_in; (void)out_size;
    const float* encoder_out = (const float*)d_in[0];  // [8,200,512]
    const float* decoder_out = (const float*)d_in[1];  // [8,50,512]
    const float* W_enc       = (const float*)d_in[2];  // [512,512]
    const float* b_enc       = (const float*)d_in[3];  // [512]
    const float* W_dec       = (const float*)d_in[4];  // [512,512]
    const float* b_dec       = (const float*)d_in[5];  // [512]
    const float* W_out       = (const float*)d_in[6];  // [500,512]
    const float* b_out       = (const float*)d_in[7];  // [500]
    float* out = (float*)d_out;                        // [8,200,50,500]

    float* encP = nullptr;
    float* decP = nullptr;
    cudaGetSymbolAddress((void**)&encP, g_encP);
    cudaGetSymbolAddress((void**)&decP, g_decP);

    // enc projection: M=1600
    {
        dim3 grid(8, 25);     // 512/64 x 1600/64
        proj_kernel<<<grid, 256>>>(encoder_out, W_enc, b_enc, encP, NT_);
    }
    // dec projection: M=400
    {
        dim3 grid(8, 7);      // 512/64 x ceil(400/64)
        proj_kernel<<<grid, 256>>>(decoder_out, W_dec, b_dec, decP, NU_);
    }
    // main fused tanh + GEMM
    {
        dim3 grid(4, 1250);   // ceil(500/128) x 80000/64
        joiner_main<<<grid, 256>>>(W_out, b_out, out);
    }
}

// round 2
// speedup vs baseline: 1.0037x; 1.0037x over previous
#include <cuda_runtime.h>
#include <cstdint>

// Problem shape (fixed by the dataset)
#define NB_ 8
#define T_  200
#define U_  50
#define J_  512
#define V_  500
#define NT_ (NB_*T_)   // 1600
#define NU_ (NB_*U_)   // 400
// rows of the big GEMM: NT_*U_ = 80000, divisible by 64 -> grid 1250

// Scratch for projected encoder/decoder (bias folded in)
__device__ float g_encP[NT_*J_];   // [1600][512]
__device__ float g_decP[NU_*J_];   // [400][512]

// ---------------------------------------------------------------------------
// Projection GEMM: C[m][j] = sum_k A[m][k] * W[j][k] + bias[j],  K = N = 512
// 64x64 tile, 4x4 per thread, 256 threads. Small kernels (~1 GF total).
// ---------------------------------------------------------------------------
__global__ __launch_bounds__(256) void proj_kernel(
    const float* __restrict__ A, const float* __restrict__ W,
    const float* __restrict__ bias, float* __restrict__ C, int M)
{
    __shared__ __align__(16) float As[64][17];
    __shared__ __align__(16) float Ws[64][17];

    const int tid = threadIdx.x;
    const int tx  = tid & 15;        // col group
    const int ty  = tid >> 4;        // row group
    const int m0  = blockIdx.y * 64;
    const int j0  = blockIdx.x * 64;
    const int lr  = tid >> 2;        // 0..63 : row loaded by this thread
    const int lk  = (tid & 3) * 4;   // 0,4,8,12 : k offset (float4)

    float acc[4][4];
#pragma unroll
    for (int i = 0; i < 4; i++)
#pragma unroll
        for (int j = 0; j < 4; j++) acc[i][j] = 0.f;

    for (int k0 = 0; k0 < 512; k0 += 16) {
        float4 av = make_float4(0.f, 0.f, 0.f, 0.f);
        if (m0 + lr < M)
            av = *(const float4*)(A + (size_t)(m0 + lr) * 512 + k0 + lk);
        float4 wv = *(const float4*)(W + (size_t)(j0 + lr) * 512 + k0 + lk);

        __syncthreads();
        As[lr][lk+0] = av.x; As[lr][lk+1] = av.y; As[lr][lk+2] = av.z; As[lr][lk+3] = av.w;
        Ws[lr][lk+0] = wv.x; Ws[lr][lk+1] = wv.y; Ws[lr][lk+2] = wv.z; Ws[lr][lk+3] = wv.w;
        __syncthreads();

#pragma unroll
        for (int k = 0; k < 16; k++) {
            float a[4], b[4];
#pragma unroll
            for (int i = 0; i < 4; i++) a[i] = As[ty + 16*i][k];
#pragma unroll
            for (int j = 0; j < 4; j++) b[j] = Ws[tx + 16*j][k];
#pragma unroll
            for (int i = 0; i < 4; i++)
#pragma unroll
                for (int j = 0; j < 4; j++)
                    acc[i][j] = fmaf(a[i], b[j], acc[i][j]);
        }
    }

#pragma unroll
    for (int i = 0; i < 4; i++) {
        int m = m0 + ty + 16*i;
        if (m >= M) continue;
#pragma unroll
        for (int j = 0; j < 4; j++) {
            int jj = j0 + tx + 16*j;               // < 512 always
            C[(size_t)m * 512 + jj] = acc[i][j] + bias[jj];
        }
    }
}

// ---------------------------------------------------------------------------
// Main fused kernel:
//   out[row][v] = sum_k tanh(encP[nt][k] + decP[n*U+u][k]) * Wout[v][k] + bout[v]
// row = nt*U + u, 80000 rows. Tile: 64 rows x 128 vocab cols, 256 threads,
// per-thread 4 rows x 4 f32x2 column-pairs (fma.rn.f32x2 -> full-rate fp32).
// ---------------------------------------------------------------------------
__global__ __launch_bounds__(256) void joiner_main(
    const float* __restrict__ Wout,   // [500][512]
    const float* __restrict__ bout,   // [500]
    float* __restrict__ out)          // [80000][500]
{
    __shared__ __align__(16) float As[64][17];    // act, [m][k]
    __shared__ __align__(16) float Bs[16][132];   // W,   [k][v] (pad 132)

    const int tid = threadIdx.x;
    const int tx  = tid & 15;
    const int ty  = tid >> 4;
    const long r0 = (long)blockIdx.y * 64;        // row base (grid.y = 1250, exact)
    const int v0  = blockIdx.x * 128;             // vocab base (grid.x = 4)

    const int lr = tid >> 2;                      // 0..63
    const int lk = (tid & 3) * 4;                 // 0,4,8,12

    // row this thread stages into As
    const long row = r0 + lr;                     // always < 80000
    const int nt = (int)(row / U_);
    const int u  = (int)(row - (long)nt * U_);
    const int n  = nt / T_;
    const float* encRow = g_encP + (size_t)nt * 512;
    const float* decRow = g_decP + ((size_t)n * U_ + u) * 512;

    // W rows this thread stages into Bs (two of them)
    const int vA = v0 + lr;
    const int vB = v0 + 64 + lr;
    const float* wRowA = (vA < V_) ? (Wout + (size_t)vA * 512) : nullptr;
    const float* wRowB = (vB < V_) ? (Wout + (size_t)vB * 512) : nullptr;

    unsigned long long acc[4][4];   // f32x2 accumulators: 4 rows x 4 col-pairs
#pragma unroll
    for (int i = 0; i < 4; i++)
#pragma unroll
        for (int jp = 0; jp < 4; jp++) acc[i][jp] = 0ull;

    for (int k0 = 0; k0 < 512; k0 += 16) {
        // activation fragment: tanh(enc + dec), 4 consecutive k for one row
        float4 e = *(const float4*)(encRow + k0 + lk);
        float4 d = *(const float4*)(decRow + k0 + lk);
        float4 av;
        av.x = tanhf(e.x + d.x);
        av.y = tanhf(e.y + d.y);
        av.z = tanhf(e.z + d.z);
        av.w = tanhf(e.w + d.w);

        float4 w0 = make_float4(0.f, 0.f, 0.f, 0.f);
        float4 w1 = make_float4(0.f, 0.f, 0.f, 0.f);
        if (wRowA) w0 = *(const float4*)(wRowA + k0 + lk);
        if (wRowB) w1 = *(const float4*)(wRowB + k0 + lk);

        __syncthreads();
        As[lr][lk+0] = av.x; As[lr][lk+1] = av.y; As[lr][lk+2] = av.z; As[lr][lk+3] = av.w;
        Bs[lk+0][lr] = w0.x; Bs[lk+1][lr] = w0.y; Bs[lk+2][lr] = w0.z; Bs[lk+3][lr] = w0.w;
        Bs[lk+0][64+lr] = w1.x; Bs[lk+1][64+lr] = w1.y; Bs[lk+2][64+lr] = w1.z; Bs[lk+3][64+lr] = w1.w;
        __syncthreads();

#pragma unroll
        for (int k = 0; k < 16; k++) {
            unsigned long long a2[4], b2[4];
#pragma unroll
            for (int i = 0; i < 4; i++) {
                float a = As[ty + 16*i][k];                 // broadcast across half-warp
                asm("mov.b64 %0, {%1, %1};" : "=l"(a2[i]) : "f"(a));
            }
#pragma unroll
            for (int jp = 0; jp < 4; jp++)                   // contiguous 8B/lane, conflict-free
                b2[jp] = *(const unsigned long long*)&Bs[k][32*jp + 2*tx];
#pragma unroll
            for (int i = 0; i < 4; i++)
#pragma unroll
                for (int jp = 0; jp < 4; jp++)
                    asm("fma.rn.f32x2 %0, %1, %2, %0;"
                        : "+l"(acc[i][jp]) : "l"(a2[i]), "l"(b2[jp]));
        }
    }

    // epilogue
#pragma unroll
    for (int i = 0; i < 4; i++) {
        const long rr = r0 + ty + 16*i;                      // < 80000 always
        float* orow = out + rr * (long)V_;
#pragma unroll
        for (int jp = 0; jp < 4; jp++) {
            const int v = v0 + 32*jp + 2*tx;
            float2 res = *(float2*)&acc[i][jp];              // .x = col v, .y = col v+1
            if (v < V_)     orow[v]     = res.x + bout[v];
            if (v + 1 < V_) orow[v + 1] = res.y + bout[v + 1];
        }
    }
}

// ---------------------------------------------------------------------------
extern "C" void kernel_launch(void* const* d_in, const int* in_sizes, int n_in,
                              void* d_out, int out_size)
{
    (void)in_sizes; (void)n_in; (void)out_size;
    const float* encoder_out = (const float*)d_in[0];  // [8,200,512]
    const float* decoder_out = (const float*)d_in[1];  // [8,50,512]
    const float* W_enc       = (const float*)d_in[2];  // [512,512]
    const float* b_enc       = (const float*)d_in[3];  // [512]
    const float* W_dec       = (const float*)d_in[4];  // [512,512]
    const float* b_dec       = (const float*)d_in[5];  // [512]
    const float* W_out       = (const float*)d_in[6];  // [500,512]
    const float* b_out       = (const float*)d_in[7];  // [500]
    float* out = (float*)d_out;                        // [8,200,50,500]

    float* encP = nullptr;
    float* decP = nullptr;
    cudaGetSymbolAddress((void**)&encP, g_encP);
    cudaGetSymbolAddress((void**)&decP, g_decP);

    // enc projection: M=1600
    {
        dim3 grid(8, 25);     // 512/64 x 1600/64
        proj_kernel<<<grid, 256>>>(encoder_out, W_enc, b_enc, encP, NT_);
    }
    // dec projection: M=400
    {
        dim3 grid(8, 7);      // 512/64 x ceil(400/64)
        proj_kernel<<<grid, 256>>>(decoder_out, W_dec, b_dec, decP, NU_);
    }
    // main fused tanh + GEMM
    {
        dim3 grid(4, 1250);   // ceil(500/128) x 80000/64
        joiner_main<<<grid, 256>>>(W_out, b_out, out);
    }
}

// round 5
// speedup vs baseline: 1.6602x; 1.6540x over previous
#include <cuda_runtime.h>
#include <cstdint>

// Problem shape (fixed by the dataset)
#define NB_ 8
#define T_  200
#define U_  50
#define J_  512
#define V_  500
#define NT_ (NB_*T_)   // 1600
#define NU_ (NB_*U_)   // 400
// rows of the big GEMM: NT_*U_ = 80000 = 625 * 128

// Scratch for projected encoder/decoder (bias folded in)
__device__ float g_encP[NT_*J_];   // [1600][512]
__device__ float g_decP[NU_*J_];   // [400][512]

__device__ __forceinline__ uint32_t f2tf32(float x) {
    uint32_t r;
    asm("cvt.rna.tf32.f32 %0, %1;" : "=r"(r) : "f"(x));
    return r;
}

// ---------------------------------------------------------------------------
// Projection GEMM (known-good): C = A * W^T + bias, K = N = 512
// ---------------------------------------------------------------------------
__global__ __launch_bounds__(256) void proj_kernel(
    const float* __restrict__ A, const float* __restrict__ W,
    const float* __restrict__ bias, float* __restrict__ C, int M)
{
    __shared__ __align__(16) float As[64][17];
    __shared__ __align__(16) float Ws[64][17];

    const int tid = threadIdx.x;
    const int tx  = tid & 15;
    const int ty  = tid >> 4;
    const int m0  = blockIdx.y * 64;
    const int j0  = blockIdx.x * 64;
    const int lr  = tid >> 2;
    const int lk  = (tid & 3) * 4;

    float acc[4][4];
#pragma unroll
    for (int i = 0; i < 4; i++)
#pragma unroll
        for (int j = 0; j < 4; j++) acc[i][j] = 0.f;

    for (int k0 = 0; k0 < 512; k0 += 16) {
        float4 av = make_float4(0.f, 0.f, 0.f, 0.f);
        if (m0 + lr < M)
            av = *(const float4*)(A + (size_t)(m0 + lr) * 512 + k0 + lk);
        float4 wv = *(const float4*)(W + (size_t)(j0 + lr) * 512 + k0 + lk);

        __syncthreads();
        As[lr][lk+0] = av.x; As[lr][lk+1] = av.y; As[lr][lk+2] = av.z; As[lr][lk+3] = av.w;
        Ws[lr][lk+0] = wv.x; Ws[lr][lk+1] = wv.y; Ws[lr][lk+2] = wv.z; Ws[lr][lk+3] = wv.w;
        __syncthreads();

#pragma unroll
        for (int k = 0; k < 16; k++) {
            float a[4], b[4];
#pragma unroll
            for (int i = 0; i < 4; i++) a[i] = As[ty + 16*i][k];
#pragma unroll
            for (int j = 0; j < 4; j++) b[j] = Ws[tx + 16*j][k];
#pragma unroll
            for (int i = 0; i < 4; i++)
#pragma unroll
                for (int j = 0; j < 4; j++)
                    acc[i][j] = fmaf(a[i], b[j], acc[i][j]);
        }
    }

#pragma unroll
    for (int i = 0; i < 4; i++) {
        int m = m0 + ty + 16*i;
        if (m >= M) continue;
#pragma unroll
        for (int j = 0; j < 4; j++) {
            int jj = j0 + tx + 16*j;
            C[(size_t)m * 512 + jj] = acc[i][j] + bias[jj];
        }
    }
}

// ---------------------------------------------------------------------------
// Main fused kernel, tensor-core path via baseline-PTX mma.sync (tf32):
//   out[row][v] = sum_k tanh(encP[nt][k] + decP[...][k]) * Wout[v][k] + bout[v]
//
// CTA tile 128 rows x 128 vocab, BK=32, grid (4, 625). 8 warps: warpM = wid&1
// (64 rows), warpN = wid>>1 (32 cols); warp tile = 4x4 m16n8k8 atoms.
// A and B are staged into smem PRE-PACKED IN FRAGMENT ORDER (tf32-converted),
// so consumers fetch fragments with a single LDS.128 (A) / LDS.64 (B).
//
// A_s layout: [matom(8)][kstep(4)][lane(32)][reg(4)]  (16 KB)
//   reg = half*2 + top;  a0:(r,c) a1:(r+8,c) a2:(r,c+4) a3:(r+8,c+4)
//   lane = (row%8)*4 + (k%4);  half = (k%8)>>2;  top = (row%16)>>3
// B_s layout: [natom(16)][kstep(4)][lane(32)][reg(2)]  (16 KB)
//   b0:(k,n) k=lane%4, n=lane>>2;  b1: k+4.  half=(k%8)>>2
// ---------------------------------------------------------------------------
__global__ __launch_bounds__(256, 2) void joiner_mma(
    const float* __restrict__ Wout,   // [500][512]
    const float* __restrict__ bout,   // [500]
    float* __restrict__ out)          // [80000][500]
{
    __shared__ __align__(16) uint32_t A_s[8 * 4 * 32 * 4];   // 16 KB
    __shared__ __align__(16) uint32_t B_s[16 * 4 * 32 * 2];  // 16 KB

    const int tid  = threadIdx.x;
    const int wid  = tid >> 5;
    const int lane = tid & 31;
    const long r0  = (long)blockIdx.y * 128;
    const int v0   = blockIdx.x * 128;

    const int warpM = wid & 1;    // 0..1
    const int warpN = wid >> 1;   // 0..3

    // --- staging assignment (both A and B): thread -> (row, 16-k half) ---
    const int srow  = tid >> 1;          // 0..127
    const int skoff = (tid & 1) * 16;    // 0 or 16

    // A source row
    const long row = r0 + srow;          // < 80000 always
    const int nt = (int)(row / U_);
    const int uu = (int)(row - (long)nt * U_);
    const int nn = nt / T_;
    const float* encRow = g_encP + (size_t)nt * J_;
    const float* decRow = g_decP + ((size_t)nn * U_ + uu) * J_;

    // B source row
    const int v = v0 + srow;
    const bool vok = (v < V_);
    const float* wRow = Wout + (size_t)v * J_;

    // precomputed fragment-packing bases
    const int a_matom = srow >> 4;
    const int a_top   = (srow >> 3) & 1;
    const int a_lane0 = (srow & 7) * 4;
    const int b_natom = srow >> 3;
    const int b_lane0 = (srow & 7) * 4;

    float acc[4][4][4];
#pragma unroll
    for (int i = 0; i < 4; i++)
#pragma unroll
        for (int j = 0; j < 4; j++)
#pragma unroll
            for (int c = 0; c < 4; c++) acc[i][j][c] = 0.f;

    for (int kc = 0; kc < 16; kc++) {
        const int k0 = kc * 32;

        // ---- produce A chunk: tanh(enc+dec) -> tf32 -> fragment-packed smem
#pragma unroll
        for (int q = 0; q < 4; q++) {
            const int kk = skoff + q * 4;            // local k, multiple of 4
            float4 e = *(const float4*)(encRow + k0 + kk);
            float4 d = *(const float4*)(decRow + k0 + kk);
            uint32_t t0 = f2tf32(tanhf(e.x + d.x));
            uint32_t t1 = f2tf32(tanhf(e.y + d.y));
            uint32_t t2 = f2tf32(tanhf(e.z + d.z));
            uint32_t t3 = f2tf32(tanhf(e.w + d.w));
            const int s    = kk >> 3;
            const int half = (kk & 7) >> 2;
            const int reg  = half * 2 + a_top;
            uint32_t* p = &A_s[(((a_matom * 4 + s) * 32) + a_lane0) * 4 + reg];
            p[0]  = t0; p[4]  = t1; p[8]  = t2; p[12] = t3;   // lane stride = 4 regs
        }
        // ---- stage B chunk: Wout -> tf32 -> fragment-packed smem
#pragma unroll
        for (int q = 0; q < 4; q++) {
            const int kk = skoff + q * 4;
            float4 w = vok ? *(const float4*)(wRow + k0 + kk)
                           : make_float4(0.f, 0.f, 0.f, 0.f);
            uint32_t t0 = f2tf32(w.x);
            uint32_t t1 = f2tf32(w.y);
            uint32_t t2 = f2tf32(w.z);
            uint32_t t3 = f2tf32(w.w);
            const int s    = kk >> 3;
            const int half = (kk & 7) >> 2;
            uint32_t* p = &B_s[(((b_natom * 4 + s) * 32) + b_lane0) * 2 + half];
            p[0] = t0; p[2] = t1; p[4] = t2; p[6] = t3;       // lane stride = 2 regs
        }
        __syncthreads();

        // ---- consume: 4 k-steps of m16n8k8
#pragma unroll
        for (int s = 0; s < 4; s++) {
            uint32_t af[4][4];
            uint32_t bf[4][2];
#pragma unroll
            for (int i = 0; i < 4; i++) {
                const uint4 va = *(const uint4*)
                    &A_s[(((warpM * 4 + i) * 4 + s) * 32 + lane) * 4];
                af[i][0] = va.x; af[i][1] = va.y; af[i][2] = va.z; af[i][3] = va.w;
            }
#pragma unroll
            for (int j = 0; j < 4; j++) {
                const uint2 vb = *(const uint2*)
                    &B_s[(((warpN * 4 + j) * 4 + s) * 32 + lane) * 2];
                bf[j][0] = vb.x; bf[j][1] = vb.y;
            }
#pragma unroll
            for (int i = 0; i < 4; i++)
#pragma unroll
                for (int j = 0; j < 4; j++) {
                    asm volatile(
                        "mma.sync.aligned.m16n8k8.row.col.f32.tf32.tf32.f32 "
                        "{%0,%1,%2,%3}, {%4,%5,%6,%7}, {%8,%9}, {%0,%1,%2,%3};"
                        : "+f"(acc[i][j][0]), "+f"(acc[i][j][1]),
                          "+f"(acc[i][j][2]), "+f"(acc[i][j][3])
                        : "r"(af[i][0]), "r"(af[i][1]), "r"(af[i][2]), "r"(af[i][3]),
                          "r"(bf[j][0]), "r"(bf[j][1]));
                }
        }
        __syncthreads();
    }

    // ---- epilogue: register -> gmem, +bias, float2 stores
    const int cpair = (lane & 3) * 2;
    const int rsub  = lane >> 2;
#pragma unroll
    for (int j = 0; j < 4; j++) {
        const int col = v0 + (warpN * 4 + j) * 8 + cpair;
        if (col >= V_) continue;                       // V_ even: pair never straddles
        const float2 bb = *(const float2*)(bout + col);
#pragma unroll
        for (int i = 0; i < 4; i++) {
            const long rr = r0 + (warpM * 4 + i) * 16 + rsub;
            float2 o0, o1;
            o0.x = acc[i][j][0] + bb.x;
            o0.y = acc[i][j][1] + bb.y;
            o1.x = acc[i][j][2] + bb.x;
            o1.y = acc[i][j][3] + bb.y;
            *(float2*)(out + rr * (long)V_ + col)       = o0;
            *(float2*)(out + (rr + 8) * (long)V_ + col) = o1;
        }
    }
}

// ---------------------------------------------------------------------------
extern "C" void kernel_launch(void* const* d_in, const int* in_sizes, int n_in,
                              void* d_out, int out_size)
{
    (void)in_sizes; (void)n_in; (void)out_size;
    const float* encoder_out = (const float*)d_in[0];  // [8,200,512]
    const float* decoder_out = (const float*)d_in[1];  // [8,50,512]
    const float* W_enc       = (const float*)d_in[2];  // [512,512]
    const float* b_enc       = (const float*)d_in[3];  // [512]
    const float* W_dec       = (const float*)d_in[4];  // [512,512]
    const float* b_dec       = (const float*)d_in[5];  // [512]
    const float* W_out       = (const float*)d_in[6];  // [500,512]
    const float* b_out       = (const float*)d_in[7];  // [500]
    float* out = (float*)d_out;                        // [8,200,50,500]

    float* encP = nullptr;
    float* decP = nullptr;
    cudaGetSymbolAddress((void**)&encP, g_encP);
    cudaGetSymbolAddress((void**)&decP, g_decP);

    // enc projection: M=1600
    {
        dim3 grid(8, 25);
        proj_kernel<<<grid, 256>>>(encoder_out, W_enc, b_enc, encP, NT_);
    }
    // dec projection: M=400
    {
        dim3 grid(8, 7);
        proj_kernel<<<grid, 256>>>(decoder_out, W_dec, b_dec, decP, NU_);
    }
    // main fused tanh + tf32 mma.sync GEMM
    {
        dim3 grid(4, 625);   // N-tiles x M-tiles
        joiner_mma<<<grid, 256>>>(W_out, b_out, out);
    }
}

// round 7
// speedup vs baseline: 2.0136x; 1.2129x over previous
#include <cuda_runtime.h>
#include <cstdint>

// Problem shape (fixed by the dataset)
#define NB_ 8
#define T_  200
#define U_  50
#define J_  512
#define V_  500
#define NT_ (NB_*T_)   // 1600
#define NU_ (NB_*U_)   // 400
// rows of the big GEMM: NT_*U_ = 80000 = 625 * 128

// Scratch for projected encoder/decoder (bias folded in)
__device__ float g_encP[NT_*J_];   // [1600][512]
__device__ float g_decP[NU_*J_];   // [400][512]

__device__ __forceinline__ uint32_t f2tf32(float x) {
    uint32_t r;
    asm("cvt.rna.tf32.f32 %0, %1;" : "=r"(r) : "f"(x));
    return r;
}
// fast tanh: 1 - 2/(e^{2x}+1)  (2 MUFU + few FMA, rel err ~2^-21, saturates right)
__device__ __forceinline__ float ftanh(float x) {
    float e = __expf(x + x);
    return 1.f - __fdividef(2.f, e + 1.f);
}

// ---------------------------------------------------------------------------
// Merged projection GEMM: C = A * W^T + bias, K = N = 512 (enc and dec tiles)
// ---------------------------------------------------------------------------
__global__ __launch_bounds__(256) void proj_both(
    const float* __restrict__ enc, const float* __restrict__ Wenc,
    const float* __restrict__ benc, float* __restrict__ encP,
    const float* __restrict__ dec, const float* __restrict__ Wdec,
    const float* __restrict__ bdec, float* __restrict__ decP)
{
    __shared__ __align__(16) float As[64][17];
    __shared__ __align__(16) float Ws[64][17];

    const float *A, *W, *bias; float* C; int M, m0;
    if (blockIdx.y < 25) { A = enc; W = Wenc; bias = benc; C = encP; M = NT_; m0 = blockIdx.y * 64; }
    else                 { A = dec; W = Wdec; bias = bdec; C = decP; M = NU_; m0 = (blockIdx.y - 25) * 64; }

    const int tid = threadIdx.x;
    const int tx  = tid & 15;
    const int ty  = tid >> 4;
    const int j0  = blockIdx.x * 64;
    const int lr  = tid >> 2;
    const int lk  = (tid & 3) * 4;

    float acc[4][4];
#pragma unroll
    for (int i = 0; i < 4; i++)
#pragma unroll
        for (int j = 0; j < 4; j++) acc[i][j] = 0.f;

    for (int k0 = 0; k0 < 512; k0 += 16) {
        float4 av = make_float4(0.f, 0.f, 0.f, 0.f);
        if (m0 + lr < M)
            av = *(const float4*)(A + (size_t)(m0 + lr) * 512 + k0 + lk);
        float4 wv = *(const float4*)(W + (size_t)(j0 + lr) * 512 + k0 + lk);

        __syncthreads();
        As[lr][lk+0] = av.x; As[lr][lk+1] = av.y; As[lr][lk+2] = av.z; As[lr][lk+3] = av.w;
        Ws[lr][lk+0] = wv.x; Ws[lr][lk+1] = wv.y; Ws[lr][lk+2] = wv.z; Ws[lr][lk+3] = wv.w;
        __syncthreads();

#pragma unroll
        for (int k = 0; k < 16; k++) {
            float a[4], b[4];
#pragma unroll
            for (int i = 0; i < 4; i++) a[i] = As[ty + 16*i][k];
#pragma unroll
            for (int j = 0; j < 4; j++) b[j] = Ws[tx + 16*j][k];
#pragma unroll
            for (int i = 0; i < 4; i++)
#pragma unroll
                for (int j = 0; j < 4; j++)
                    acc[i][j] = fmaf(a[i], b[j], acc[i][j]);
        }
    }

#pragma unroll
    for (int i = 0; i < 4; i++) {
        int m = m0 + ty + 16*i;
        if (m >= M) continue;
#pragma unroll
        for (int j = 0; j < 4; j++) {
            int jj = j0 + tx + 16*j;
            C[(size_t)m * 512 + jj] = acc[i][j] + bias[jj];
        }
    }
}

// ---------------------------------------------------------------------------
// Main fused kernel (tf32 mma.sync, fragment-order smem, double-buffered):
//   out[row][v] = sum_k tanh(encP[nt][k] + decP[...][k]) * Wout[v][k] + bout[v]
//
// CTA tile 128 rows x 256 vocab, BK=32, grid (2, 625). 8 warps: warpM=wid&1
// (64 rows), warpN=wid>>1 (64 cols); warp tile 4x8 m16n8k8 atoms, acc=128 regs.
//
// Smem per buffer (48KB, x2 buffers = 96KB dynamic):
//   A_s: [matom(8)][s(4)][lane(32)][reg(4)] u32   (16KB)
//        lane l of (matom,s): a0=Act[16m+(l>>2)][8s+(l&3)], a1=row+8,
//        a2=col+4, a3=both  (validated fragment order from R4)
//   B_s: [natom(32)][s(4)][lane(32)][reg(2)] u32  (32KB)
//        lane l: b0=W[v0+8n+(l>>2)][8s+(l&3)], b1=col+4
// Staging writes whole 16B fragment words (STS.128) with issue-order rotation
// so each 8-lane phase covers 8 distinct 16B banks-groups (conflict-free).
// ---------------------------------------------------------------------------
#define SMEM_BYTES (2 * 49152)      // 96 KB
// u32 offsets within dynamic smem
#define A_U32(buf) ((buf) * 12288)
#define B_U32(buf) ((buf) * 12288 + 4096)

__global__ __launch_bounds__(256, 1) void joiner_mma(
    const float* __restrict__ Wout,   // [500][512]
    const float* __restrict__ bout,   // [500]
    float* __restrict__ out)          // [80000][500]
{
    extern __shared__ __align__(16) uint32_t smem[];

    const int tid  = threadIdx.x;
    const int wid  = tid >> 5;
    const int lane = tid & 31;
    const long r0  = (long)blockIdx.y * 128;
    const int v0   = blockIdx.x * 256;
    const int warpM = wid & 1;    // 0..1
    const int warpN = wid >> 1;   // 0..3

    // ---- A staging identity: thread = (matom, pair, s) ----
    const int sa_matom = tid >> 5;        // 0..7
    const int sa_pair  = (tid >> 2) & 7;  // 0..7
    const int sa_s     = tid & 3;         // 0..3
    const int rA0 = sa_matom * 16 + sa_pair;          // local row
    // global rows rA0 and rA0+8
    const long rowA0 = r0 + rA0;
    const long rowA1 = rowA0 + 8;
    const int nt0 = (int)(rowA0 / U_);
    const int u0  = (int)(rowA0 - (long)nt0 * U_);
    const int n0  = nt0 / T_;
    const int nt1 = (int)(rowA1 / U_);
    const int u1  = (int)(rowA1 - (long)nt1 * U_);
    const int n1  = nt1 / T_;
    const float* encR0 = g_encP + (size_t)nt0 * J_;
    const float* decR0 = g_decP + ((size_t)n0 * U_ + u0) * J_;
    const float* encR1 = g_encP + (size_t)nt1 * J_;
    const float* decR1 = g_decP + ((size_t)n1 * U_ + u1) * J_;
    // base u32 index of this thread's (matom, s) fragment row
    const int a_base = (sa_matom * 4 + sa_s) * 128 + sa_pair * 16;  // *4 regs per lane

    // ---- B staging identity: thread = (natom, nlocal); v = v0 + tid ----
    const int sb_natom  = tid >> 3;       // 0..31
    const int sb_nlocal = tid & 7;        // 0..7
    const int vB = v0 + tid;
    const bool vok = (vB < V_);
    const float* wRow = Wout + (size_t)vB * J_;
    const int hrot = (sb_nlocal >> 2) & 1;

    float acc[4][8][4];
#pragma unroll
    for (int i = 0; i < 4; i++)
#pragma unroll
        for (int j = 0; j < 8; j++)
#pragma unroll
            for (int c = 0; c < 4; c++) acc[i][j][c] = 0.f;

    // ================= staging helpers (inline lambdas) =================
    auto stageA = [&](int kc, int buf) {
        const int c0 = kc * 32 + sa_s * 8;
        float4 e0a = *(const float4*)(encR0 + c0);
        float4 e0b = *(const float4*)(encR0 + c0 + 4);
        float4 d0a = *(const float4*)(decR0 + c0);
        float4 d0b = *(const float4*)(decR0 + c0 + 4);
        float4 e1a = *(const float4*)(encR1 + c0);
        float4 e1b = *(const float4*)(encR1 + c0 + 4);
        float4 d1a = *(const float4*)(decR1 + c0);
        float4 d1b = *(const float4*)(decR1 + c0 + 4);
        uint32_t t0[8], t1[8];
        t0[0] = f2tf32(ftanh(e0a.x + d0a.x));
        t0[1] = f2tf32(ftanh(e0a.y + d0a.y));
        t0[2] = f2tf32(ftanh(e0a.z + d0a.z));
        t0[3] = f2tf32(ftanh(e0a.w + d0a.w));
        t0[4] = f2tf32(ftanh(e0b.x + d0b.x));
        t0[5] = f2tf32(ftanh(e0b.y + d0b.y));
        t0[6] = f2tf32(ftanh(e0b.z + d0b.z));
        t0[7] = f2tf32(ftanh(e0b.w + d0b.w));
        t1[0] = f2tf32(ftanh(e1a.x + d1a.x));
        t1[1] = f2tf32(ftanh(e1a.y + d1a.y));
        t1[2] = f2tf32(ftanh(e1a.z + d1a.z));
        t1[3] = f2tf32(ftanh(e1a.w + d1a.w));
        t1[4] = f2tf32(ftanh(e1b.x + d1b.x));
        t1[5] = f2tf32(ftanh(e1b.y + d1b.y));
        t1[6] = f2tf32(ftanh(e1b.z + d1b.z));
        t1[7] = f2tf32(ftanh(e1b.w + d1b.w));
        uint32_t* base = smem + A_U32(buf) + a_base;
#pragma unroll
        for (int q = 0; q < 4; q++) {
            const int kk = (q + sa_s) & 3;               // bank-rotation issue order
            uint4 w4;
            w4.x = t0[kk]; w4.y = t1[kk]; w4.z = t0[kk + 4]; w4.w = t1[kk + 4];
            *(uint4*)(base + kk * 4) = w4;
        }
    };
    // ====================================================================

    // -------- prologue: stage chunk 0 into buffer 0 --------
    {
        stageA(0, 0);
        float4 wv[4][2];
#pragma unroll
        for (int s = 0; s < 4; s++) {
            const int c0 = s * 8;
            wv[s][0] = vok ? *(const float4*)(wRow + c0)     : make_float4(0,0,0,0);
            wv[s][1] = vok ? *(const float4*)(wRow + c0 + 4) : make_float4(0,0,0,0);
        }
        uint32_t* bbase = smem + B_U32(0) + sb_natom * 256 + sb_nlocal * 8;
#pragma unroll
        for (int s = 0; s < 4; s++)
#pragma unroll
            for (int hh = 0; hh < 2; hh++) {
                const int h = hh ^ hrot;
                uint4 w4;
                const float* p0 = &wv[s][0].x;
                const float* p1 = &wv[s][1].x;
                w4.x = f2tf32(p0[2*h]);   w4.y = f2tf32(p1[2*h]);
                w4.z = f2tf32(p0[2*h+1]); w4.w = f2tf32(p1[2*h+1]);
                *(uint4*)(bbase + s * 64 + h * 4) = w4;
            }
    }
    __syncthreads();

    // -------- main loop: 16 chunks of K=32, double-buffered --------
#pragma unroll 1
    for (int kc = 0; kc < 16; kc++) {
        const int cur = kc & 1;

        // issue next chunk's W loads early (hide L2 latency under HMMA)
        float4 wv[4][2];
        if (kc < 15) {
            const int c0 = (kc + 1) * 32;
#pragma unroll
            for (int s = 0; s < 4; s++) {
                wv[s][0] = vok ? *(const float4*)(wRow + c0 + s * 8)     : make_float4(0,0,0,0);
                wv[s][1] = vok ? *(const float4*)(wRow + c0 + s * 8 + 4) : make_float4(0,0,0,0);
            }
            stageA(kc + 1, 1 - cur);
        }

        // consume current buffer: 4 k-steps of m16n8k8
        const uint32_t* Ab = smem + A_U32(cur);
        const uint32_t* Bb = smem + B_U32(cur);
#pragma unroll
        for (int s = 0; s < 4; s++) {
            uint32_t af[4][4];
            uint32_t bf[8][2];
#pragma unroll
            for (int i = 0; i < 4; i++) {
                const uint4 va = *(const uint4*)
                    (Ab + (((warpM * 4 + i) * 4 + s) * 32 + lane) * 4);
                af[i][0] = va.x; af[i][1] = va.y; af[i][2] = va.z; af[i][3] = va.w;
            }
#pragma unroll
            for (int j = 0; j < 8; j++) {
                const uint2 vb = *(const uint2*)
                    (Bb + (((warpN * 8 + j) * 4 + s) * 32 + lane) * 2);
                bf[j][0] = vb.x; bf[j][1] = vb.y;
            }
#pragma unroll
            for (int i = 0; i < 4; i++)
#pragma unroll
                for (int j = 0; j < 8; j++) {
                    asm volatile(
                        "mma.sync.aligned.m16n8k8.row.col.f32.tf32.tf32.f32 "
                        "{%0,%1,%2,%3}, {%4,%5,%6,%7}, {%8,%9}, {%0,%1,%2,%3};"
                        : "+f"(acc[i][j][0]), "+f"(acc[i][j][1]),
                          "+f"(acc[i][j][2]), "+f"(acc[i][j][3])
                        : "r"(af[i][0]), "r"(af[i][1]), "r"(af[i][2]), "r"(af[i][3]),
                          "r"(bf[j][0]), "r"(bf[j][1]));
                }
        }

        // finish staging: convert + store B for next chunk
        if (kc < 15) {
            uint32_t* bbase = smem + B_U32(1 - cur) + sb_natom * 256 + sb_nlocal * 8;
#pragma unroll
            for (int s = 0; s < 4; s++)
#pragma unroll
                for (int hh = 0; hh < 2; hh++) {
                    const int h = hh ^ hrot;
                    uint4 w4;
                    const float* p0 = &wv[s][0].x;
                    const float* p1 = &wv[s][1].x;
                    w4.x = f2tf32(p0[2*h]);   w4.y = f2tf32(p1[2*h]);
                    w4.z = f2tf32(p0[2*h+1]); w4.w = f2tf32(p1[2*h+1]);
                    *(uint4*)(bbase + s * 64 + h * 4) = w4;
                }
        }
        __syncthreads();
    }

    // -------- epilogue: registers -> gmem, +bias, float2 stores --------
    const int cpair = (lane & 3) * 2;
    const int rsub  = lane >> 2;
#pragma unroll
    for (int j = 0; j < 8; j++) {
        const int col = v0 + warpN * 64 + j * 8 + cpair;
        if (col >= V_) continue;                  // V_ even: pair never straddles
        const float2 bb = *(const float2*)(bout + col);
#pragma unroll
        for (int i = 0; i < 4; i++) {
            const long rr = r0 + warpM * 64 + i * 16 + rsub;
            float2 o0, o1;
            o0.x = acc[i][j][0] + bb.x;
            o0.y = acc[i][j][1] + bb.y;
            o1.x = acc[i][j][2] + bb.x;
            o1.y = acc[i][j][3] + bb.y;
            *(float2*)(out + rr * (long)V_ + col)       = o0;
            *(float2*)(out + (rr + 8) * (long)V_ + col) = o1;
        }
    }
}

// ---------------------------------------------------------------------------
extern "C" void kernel_launch(void* const* d_in, const int* in_sizes, int n_in,
                              void* d_out, int out_size)
{
    (void)in_sizes; (void)n_in; (void)out_size;
    const float* encoder_out = (const float*)d_in[0];  // [8,200,512]
    const float* decoder_out = (const float*)d_in[1];  // [8,50,512]
    const float* W_enc       = (const float*)d_in[2];  // [512,512]
    const float* b_enc       = (const float*)d_in[3];  // [512]
    const float* W_dec       = (const float*)d_in[4];  // [512,512]
    const float* b_dec       = (const float*)d_in[5];  // [512]
    const float* W_out       = (const float*)d_in[6];  // [500,512]
    const float* b_out       = (const float*)d_in[7];  // [500]
    float* out = (float*)d_out;                        // [8,200,50,500]

    float* encP = nullptr;
    float* decP = nullptr;
    cudaGetSymbolAddress((void**)&encP, g_encP);
    cudaGetSymbolAddress((void**)&decP, g_decP);

    cudaFuncSetAttribute(joiner_mma,
                         cudaFuncAttributeMaxDynamicSharedMemorySize, SMEM_BYTES);

    // merged projections (enc: 25 y-tiles, dec: 7 y-tiles)
    {
        dim3 grid(8, 32);
        proj_both<<<grid, 256>>>(encoder_out, W_enc, b_enc, encP,
                                 decoder_out, W_dec, b_dec, decP);
    }
    // main fused tanh + tf32 mma.sync GEMM
    {
        dim3 grid(2, 625);   // N-tiles x M-tiles
        joiner_mma<<<grid, 256, SMEM_BYTES>>>(W_out, b_out, out);
    }
}

// round 8
// speedup vs baseline: 4.4699x; 2.2198x over previous
#include <cuda_runtime.h>
#include <cuda_fp16.h>
#include <cstdint>

// Problem shape (fixed by the dataset)
#define NB_ 8
#define T_  200
#define U_  50
#define J_  512
#define V_  500
#define NT_ (NB_*T_)   // 1600
#define NU_ (NB_*U_)   // 400
// rows of the big GEMM: NT_*U_ = 80000 = 625 * 128

// Scratch
__device__ float g_encP[NT_*J_];     // [1600][512] projected enc (+bias)
__device__ float g_decP[NU_*J_];     // [400][512]  projected dec (+bias)
// W_out pre-packed to fp16 fragment order:
//   [vt(2)][natom(32)][ks(32)][lane(32)] uint2
//   lane: g=lane>>2 (n within atom), t=lane&3 (k-pair)
//   .x = {W[v][k+2t], W[v][k+2t+1]}  .y = {W[v][k+2t+8], W[v][k+2t+9]}
//   v = vt*256 + natom*8 + g, k = ks*16
__device__ uint2 g_Bh[2*32*32*32];   // 512 KB

__device__ __forceinline__ uint32_t smem_u32(const void* p) {
    uint32_t a;
    asm("{ .reg .u64 t; cvta.to.shared.u64 t, %1; cvt.u32.u64 %0, t; }"
        : "=r"(a) : "l"(p));
    return a;
}
__device__ __forceinline__ float atanh_(float x) {
    float y;
    asm("tanh.approx.f32 %0, %1;" : "=f"(y) : "f"(x));
    return y;
}
__device__ __forceinline__ uint32_t h2u(float lo, float hi) {
    __half2 h = __floats2half2_rn(lo, hi);   // .x = lo, .y = hi
    return *(uint32_t*)&h;
}

// ---------------------------------------------------------------------------
// W_out -> fp16 fragment-packed gmem (one tiny launch, 0.5 MB out)
// ---------------------------------------------------------------------------
__global__ __launch_bounds__(256) void pack_w(const float* __restrict__ W)
{
    const int idx  = blockIdx.x * 256 + threadIdx.x;   // 65536 total
    const int lane = idx & 31;
    const int ks   = (idx >> 5) & 31;
    const int na   = (idx >> 10) & 31;
    const int vt   = idx >> 15;
    const int g = lane >> 2, t = lane & 3;
    const int v = vt * 256 + na * 8 + g;
    const int k = ks * 16 + 2 * t;
    float w0 = 0.f, w1 = 0.f, w2 = 0.f, w3 = 0.f;
    if (v < V_) {
        const float* r = W + (size_t)v * J_;
        w0 = r[k]; w1 = r[k+1]; w2 = r[k+8]; w3 = r[k+9];
    }
    uint2 o;
    o.x = h2u(w0, w1);
    o.y = h2u(w2, w3);
    g_Bh[idx] = o;
}

// ---------------------------------------------------------------------------
// Merged projection GEMM: C = A * W^T + bias, K = N = 512 (enc and dec)
// ---------------------------------------------------------------------------
__global__ __launch_bounds__(256) void proj_both(
    const float* __restrict__ enc, const float* __restrict__ Wenc,
    const float* __restrict__ benc, float* __restrict__ encP,
    const float* __restrict__ dec, const float* __restrict__ Wdec,
    const float* __restrict__ bdec, float* __restrict__ decP)
{
    __shared__ __align__(16) float As[64][17];
    __shared__ __align__(16) float Ws[64][17];

    const float *A, *W, *bias; float* C; int M, m0;
    if (blockIdx.y < 25) { A = enc; W = Wenc; bias = benc; C = encP; M = NT_; m0 = blockIdx.y * 64; }
    else                 { A = dec; W = Wdec; bias = bdec; C = decP; M = NU_; m0 = (blockIdx.y - 25) * 64; }

    const int tid = threadIdx.x;
    const int tx  = tid & 15;
    const int ty  = tid >> 4;
    const int j0  = blockIdx.x * 64;
    const int lr  = tid >> 2;
    const int lk  = (tid & 3) * 4;

    float acc[4][4];
#pragma unroll
    for (int i = 0; i < 4; i++)
#pragma unroll
        for (int j = 0; j < 4; j++) acc[i][j] = 0.f;

    for (int k0 = 0; k0 < 512; k0 += 16) {
        float4 av = make_float4(0.f, 0.f, 0.f, 0.f);
        if (m0 + lr < M)
            av = *(const float4*)(A + (size_t)(m0 + lr) * 512 + k0 + lk);
        float4 wv = *(const float4*)(W + (size_t)(j0 + lr) * 512 + k0 + lk);

        __syncthreads();
        As[lr][lk+0] = av.x; As[lr][lk+1] = av.y; As[lr][lk+2] = av.z; As[lr][lk+3] = av.w;
        Ws[lr][lk+0] = wv.x; Ws[lr][lk+1] = wv.y; Ws[lr][lk+2] = wv.z; Ws[lr][lk+3] = wv.w;
        __syncthreads();

#pragma unroll
        for (int k = 0; k < 16; k++) {
            float a[4], b[4];
#pragma unroll
            for (int i = 0; i < 4; i++) a[i] = As[ty + 16*i][k];
#pragma unroll
            for (int j = 0; j < 4; j++) b[j] = Ws[tx + 16*j][k];
#pragma unroll
            for (int i = 0; i < 4; i++)
#pragma unroll
                for (int j = 0; j < 4; j++)
                    acc[i][j] = fmaf(a[i], b[j], acc[i][j]);
        }
    }

#pragma unroll
    for (int i = 0; i < 4; i++) {
        int m = m0 + ty + 16*i;
        if (m >= M) continue;
#pragma unroll
        for (int j = 0; j < 4; j++) {
            int jj = j0 + tx + 16*j;
            C[(size_t)m * 512 + jj] = acc[i][j] + bias[jj];
        }
    }
}

// ---------------------------------------------------------------------------
// Main fused kernel, fp16 m16n8k16 mma.sync:
//   out[row][v] = sum_k tanh(encP[..][k] + decP[..][k]) * Wout[v][k] + bout[v]
//
// CTA tile 128 rows x 256 vocab, BK=32 (2 ksteps of 16), grid (2, 625).
// 8 warps: warpM=wid&1 (64 rows) x warpN=wid>>1 (64 cols) = 4x8 atoms, acc 128.
//
// Smem (static, 48KB exactly, double-buffered):
//   A_s[2][matom 8][ksl 2][lane 32] uint4  (8KB/buf)
//     lane (g=l>>2,t=l&3): {h2(act[16m+g][kb+2t..]), h2(act[16m+8+g][..]),
//                           h2(act[16m+g][kb+2t+8..]), h2(act[16m+8+g][..])}
//   B_s[2][natom 32][ksl 2][lane 32] uint2 (16KB/buf) -- copied via cp.async
//     straight from the pre-packed g_Bh (fragment order already).
// ---------------------------------------------------------------------------
__global__ __launch_bounds__(256, 1) void joiner_hmma(
    const float* __restrict__ bout,   // [500]
    float* __restrict__ out)          // [80000][500]
{
    __shared__ __align__(16) uint32_t A_s[2 * 2048];   // 16 KB
    __shared__ __align__(16) uint32_t B_s[2 * 4096];   // 32 KB

    const int tid  = threadIdx.x;
    const int wid  = tid >> 5;
    const int lane = tid & 31;
    const long r0  = (long)blockIdx.y * 128;
    const int vt   = blockIdx.x;               // 0..1
    const int v0   = vt * 256;
    const int warpM = wid & 1;
    const int warpN = wid >> 1;

    // ---- A staging identity: matom = wid, g = (tid>>2)&7, t = tid&3 ----
    const int sa_m = tid >> 5;
    const int sa_g = (tid >> 2) & 7;
    const int sa_t = tid & 3;
    const long rowA0 = r0 + sa_m * 16 + sa_g;
    const long rowA1 = rowA0 + 8;
    const int nt0 = (int)(rowA0 / U_);
    const int u0  = (int)(rowA0 - (long)nt0 * U_);
    const int nt1 = (int)(rowA1 / U_);
    const int u1  = (int)(rowA1 - (long)nt1 * U_);
    const float* encR0 = g_encP + (size_t)nt0 * J_;
    const float* decR0 = g_decP + ((size_t)(nt0 / T_) * U_ + u0) * J_;
    const float* encR1 = g_encP + (size_t)nt1 * J_;
    const float* decR1 = g_decP + ((size_t)(nt1 / T_) * U_ + u1) * J_;
    // A_s u32 index for (ksl): ((sa_m*2+ksl)*32 + lane)*4, lane = tid&31
    const int a_idx0 = ((sa_m * 2 + 0) * 32 + (tid & 31)) * 4;

    // ---- B cp.async identity ----
    const int b_lp  = tid & 15;          // lane-pair (16B = 2 lanes)
    const int b_ksl = (tid >> 4) & 1;
    const int b_na0 = tid >> 5;          // + 8*q, q=0..3
    const char* bh_base = (const char*)g_Bh;
    const uint32_t smemB = smem_u32(B_s);

    float acc[4][8][4];
#pragma unroll
    for (int i = 0; i < 4; i++)
#pragma unroll
        for (int j = 0; j < 8; j++)
#pragma unroll
            for (int c = 0; c < 4; c++) acc[i][j][c] = 0.f;

    // ---- B async copy: chunk kc -> buffer buf ----
    auto copyB = [&](int kc, int buf) {
#pragma unroll
        for (int q = 0; q < 4; q++) {
            const int na = b_na0 + 8 * q;
            const long goff = (long)((vt * 32 + na) * 32 + 2 * kc + b_ksl) * 256
                              + b_lp * 16;
            const uint32_t soff = (uint32_t)buf * 16384u
                                  + (uint32_t)((na * 2 + b_ksl) * 256 + b_lp * 16);
            asm volatile("cp.async.cg.shared.global [%0], [%1], 16;"
                         :: "r"(smemB + soff), "l"(bh_base + goff));
        }
        asm volatile("cp.async.commit_group;" ::: "memory");
    };
    // ---- A load (gmem -> regs) for chunk kc ----
    float2 e0[2][2], e1[2][2], d0[2][2], d1[2][2];  // [ksl][lo/hi-8]
    auto loadA = [&](int kc) {
#pragma unroll
        for (int ksl = 0; ksl < 2; ksl++) {
            const int kb = kc * 32 + ksl * 16 + 2 * sa_t;
            e0[ksl][0] = *(const float2*)(encR0 + kb);
            e0[ksl][1] = *(const float2*)(encR0 + kb + 8);
            e1[ksl][0] = *(const float2*)(encR1 + kb);
            e1[ksl][1] = *(const float2*)(encR1 + kb + 8);
            d0[ksl][0] = *(const float2*)(decR0 + kb);
            d0[ksl][1] = *(const float2*)(decR0 + kb + 8);
            d1[ksl][0] = *(const float2*)(decR1 + kb);
            d1[ksl][1] = *(const float2*)(decR1 + kb + 8);
        }
    };
    // ---- A math + store (regs -> smem buf) ----
    auto mathA = [&](int buf) {
        uint32_t* base = A_s + buf * 2048 + a_idx0;
#pragma unroll
        for (int ksl = 0; ksl < 2; ksl++) {
            uint4 w4;
            w4.x = h2u(atanh_(e0[ksl][0].x + d0[ksl][0].x),
                       atanh_(e0[ksl][0].y + d0[ksl][0].y));
            w4.y = h2u(atanh_(e1[ksl][0].x + d1[ksl][0].x),
                       atanh_(e1[ksl][0].y + d1[ksl][0].y));
            w4.z = h2u(atanh_(e0[ksl][1].x + d0[ksl][1].x),
                       atanh_(e0[ksl][1].y + d0[ksl][1].y));
            w4.w = h2u(atanh_(e1[ksl][1].x + d1[ksl][1].x),
                       atanh_(e1[ksl][1].y + d1[ksl][1].y));
            *(uint4*)(base + ksl * 128) = w4;      // (+1 ksl) -> +32 lanes*4 u32
        }
    };

    // -------- prologue: chunk 0 into buffer 0 --------
    copyB(0, 0);
    loadA(0);
    mathA(0);
    asm volatile("cp.async.wait_group 0;" ::: "memory");
    __syncthreads();

    // -------- main loop: 16 chunks, double-buffered --------
#pragma unroll 1
    for (int kc = 0; kc < 16; kc++) {
        const int cur = kc & 1;

        if (kc < 15) {
            copyB(kc + 1, 1 - cur);    // async, in flight under consume
            loadA(kc + 1);             // LDGs issued, consumed after the MMAs
        }

        // consume current buffer: 2 ksteps of m16n8k16
        const uint32_t* Ab = A_s + cur * 2048;
        const uint32_t* Bb = B_s + cur * 4096;
#pragma unroll
        for (int ksl = 0; ksl < 2; ksl++) {
            uint32_t af[4][4];
            uint32_t bf[8][2];
#pragma unroll
            for (int i = 0; i < 4; i++) {
                const uint4 va = *(const uint4*)
                    (Ab + (((warpM * 4 + i) * 2 + ksl) * 32 + lane) * 4);
                af[i][0] = va.x; af[i][1] = va.y; af[i][2] = va.z; af[i][3] = va.w;
            }
#pragma unroll
            for (int j = 0; j < 8; j++) {
                const uint2 vb = *(const uint2*)
                    (Bb + (((warpN * 8 + j) * 2 + ksl) * 32 + lane) * 2);
                bf[j][0] = vb.x; bf[j][1] = vb.y;
            }
#pragma unroll
            for (int i = 0; i < 4; i++)
#pragma unroll
                for (int j = 0; j < 8; j++) {
                    asm volatile(
                        "mma.sync.aligned.m16n8k16.row.col.f32.f16.f16.f32 "
                        "{%0,%1,%2,%3}, {%4,%5,%6,%7}, {%8,%9}, {%0,%1,%2,%3};"
                        : "+f"(acc[i][j][0]), "+f"(acc[i][j][1]),
                          "+f"(acc[i][j][2]), "+f"(acc[i][j][3])
                        : "r"(af[i][0]), "r"(af[i][1]), "r"(af[i][2]), "r"(af[i][3]),
                          "r"(bf[j][0]), "r"(bf[j][1]));
                }
        }

        if (kc < 15) mathA(1 - cur);   // tanh + pack + STS for next chunk
        asm volatile("cp.async.wait_group 0;" ::: "memory");
        __syncthreads();
    }

    // -------- epilogue: registers -> gmem, +bias, float2 stores --------
    const int cpair = (lane & 3) * 2;
    const int rsub  = lane >> 2;
#pragma unroll
    for (int j = 0; j < 8; j++) {
        const int col = v0 + warpN * 64 + j * 8 + cpair;
        if (col >= V_) continue;                  // V_ even: pair never straddles
        const float2 bb = *(const float2*)(bout + col);
#pragma unroll
        for (int i = 0; i < 4; i++) {
            const long rr = r0 + warpM * 64 + i * 16 + rsub;
            float2 o0, o1;
            o0.x = acc[i][j][0] + bb.x;
            o0.y = acc[i][j][1] + bb.y;
            o1.x = acc[i][j][2] + bb.x;
            o1.y = acc[i][j][3] + bb.y;
            *(float2*)(out + rr * (long)V_ + col)       = o0;
            *(float2*)(out + (rr + 8) * (long)V_ + col) = o1;
        }
    }
}

// ---------------------------------------------------------------------------
extern "C" void kernel_launch(void* const* d_in, const int* in_sizes, int n_in,
                              void* d_out, int out_size)
{
    (void)in_sizes; (void)n_in; (void)out_size;
    const float* encoder_out = (const float*)d_in[0];  // [8,200,512]
    const float* decoder_out = (const float*)d_in[1];  // [8,50,512]
    const float* W_enc       = (const float*)d_in[2];  // [512,512]
    const float* b_enc       = (const float*)d_in[3];  // [512]
    const float* W_dec       = (const float*)d_in[4];  // [512,512]
    const float* b_dec       = (const float*)d_in[5];  // [512]
    const float* W_out       = (const float*)d_in[6];  // [500,512]
    const float* b_out       = (const float*)d_in[7];  // [500]
    float* out = (float*)d_out;                        // [8,200,50,500]

    float* encP = nullptr;
    float* decP = nullptr;
    cudaGetSymbolAddress((void**)&encP, g_encP);
    cudaGetSymbolAddress((void**)&decP, g_decP);

    // pack W_out to fp16 fragment order (independent of projections)
    pack_w<<<256, 256>>>(W_out);

    // merged projections (enc: 25 y-tiles, dec: 7 y-tiles)
    {
        dim3 grid(8, 32);
        proj_both<<<grid, 256>>>(encoder_out, W_enc, b_enc, encP,
                                 decoder_out, W_dec, b_dec, decP);
    }
    // main fused tanh + fp16 mma.sync GEMM
    {
        dim3 grid(2, 625);   // N-tiles x M-tiles
        joiner_hmma<<<grid, 256>>>(b_out, out);
    }
}

// round 9
// speedup vs baseline: 4.4704x; 1.0001x over previous
#include <cuda_runtime.h>
#include <cuda_fp16.h>
#include <cstdint>

// Problem shape (fixed by the dataset)
#define NB_ 8
#define T_  200
#define U_  50
#define J_  512
#define V_  500
#define NT_ (NB_*T_)   // 1600
#define NU_ (NB_*U_)   // 400
// rows of the big GEMM: NT_*U_ = 80000 = 625 * 128

// Scratch
__device__ float g_encP[NT_*J_];     // [1600][512] projected enc (+bias)
__device__ float g_decP[NU_*J_];     // [400][512]  projected dec (+bias)
// W_out pre-packed to fp16 fragment order:
//   [vt(2)][natom(32)][ks(32)][lane(32)] uint2
//   lane: g=lane>>2 (n within atom), t=lane&3 (k-pair)
//   .x = {W[v][k+2t], W[v][k+2t+1]}  .y = {W[v][k+2t+8], W[v][k+2t+9]}
//   v = vt*256 + natom*8 + g, k = ks*16
__device__ uint2 g_Bh[2*32*32*32];   // 512 KB

__device__ __forceinline__ uint32_t smem_u32(const void* p) {
    uint32_t a;
    asm("{ .reg .u64 t; cvta.to.shared.u64 t, %1; cvt.u32.u64 %0, t; }"
        : "=r"(a) : "l"(p));
    return a;
}
__device__ __forceinline__ float atanh_(float x) {
    float y;
    asm("tanh.approx.f32 %0, %1;" : "=f"(y) : "f"(x));
    return y;
}
__device__ __forceinline__ uint32_t h2u(float lo, float hi) {
    __half2 h = __floats2half2_rn(lo, hi);   // .x = lo, .y = hi
    return *(uint32_t*)&h;
}

// ---------------------------------------------------------------------------
// W_out -> fp16 fragment-packed gmem (one tiny launch, 0.5 MB out)
// ---------------------------------------------------------------------------
__global__ __launch_bounds__(256) void pack_w(const float* __restrict__ W)
{
    const int idx  = blockIdx.x * 256 + threadIdx.x;   // 65536 total
    const int lane = idx & 31;
    const int ks   = (idx >> 5) & 31;
    const int na   = (idx >> 10) & 31;
    const int vt   = idx >> 15;
    const int g = lane >> 2, t = lane & 3;
    const int v = vt * 256 + na * 8 + g;
    const int k = ks * 16 + 2 * t;
    float w0 = 0.f, w1 = 0.f, w2 = 0.f, w3 = 0.f;
    if (v < V_) {
        const float* r = W + (size_t)v * J_;
        w0 = r[k]; w1 = r[k+1]; w2 = r[k+8]; w3 = r[k+9];
    }
    uint2 o;
    o.x = h2u(w0, w1);
    o.y = h2u(w2, w3);
    g_Bh[idx] = o;
}

// ---------------------------------------------------------------------------
// Merged projection GEMM: C = A * W^T + bias, K = N = 512 (enc and dec)
// ---------------------------------------------------------------------------
__global__ __launch_bounds__(256) void proj_both(
    const float* __restrict__ enc, const float* __restrict__ Wenc,
    const float* __restrict__ benc, float* __restrict__ encP,
    const float* __restrict__ dec, const float* __restrict__ Wdec,
    const float* __restrict__ bdec, float* __restrict__ decP)
{
    __shared__ __align__(16) float As[64][17];
    __shared__ __align__(16) float Ws[64][17];

    const float *A, *W, *bias; float* C; int M, m0;
    if (blockIdx.y < 25) { A = enc; W = Wenc; bias = benc; C = encP; M = NT_; m0 = blockIdx.y * 64; }
    else                 { A = dec; W = Wdec; bias = bdec; C = decP; M = NU_; m0 = (blockIdx.y - 25) * 64; }

    const int tid = threadIdx.x;
    const int tx  = tid & 15;
    const int ty  = tid >> 4;
    const int j0  = blockIdx.x * 64;
    const int lr  = tid >> 2;
    const int lk  = (tid & 3) * 4;

    float acc[4][4];
#pragma unroll
    for (int i = 0; i < 4; i++)
#pragma unroll
        for (int j = 0; j < 4; j++) acc[i][j] = 0.f;

    for (int k0 = 0; k0 < 512; k0 += 16) {
        float4 av = make_float4(0.f, 0.f, 0.f, 0.f);
        if (m0 + lr < M)
            av = *(const float4*)(A + (size_t)(m0 + lr) * 512 + k0 + lk);
        float4 wv = *(const float4*)(W + (size_t)(j0 + lr) * 512 + k0 + lk);

        __syncthreads();
        As[lr][lk+0] = av.x; As[lr][lk+1] = av.y; As[lr][lk+2] = av.z; As[lr][lk+3] = av.w;
        Ws[lr][lk+0] = wv.x; Ws[lr][lk+1] = wv.y; Ws[lr][lk+2] = wv.z; Ws[lr][lk+3] = wv.w;
        __syncthreads();

#pragma unroll
        for (int k = 0; k < 16; k++) {
            float a[4], b[4];
#pragma unroll
            for (int i = 0; i < 4; i++) a[i] = As[ty + 16*i][k];
#pragma unroll
            for (int j = 0; j < 4; j++) b[j] = Ws[tx + 16*j][k];
#pragma unroll
            for (int i = 0; i < 4; i++)
#pragma unroll
                for (int j = 0; j < 4; j++)
                    acc[i][j] = fmaf(a[i], b[j], acc[i][j]);
        }
    }

#pragma unroll
    for (int i = 0; i < 4; i++) {
        int m = m0 + ty + 16*i;
        if (m >= M) continue;
#pragma unroll
        for (int j = 0; j < 4; j++) {
            int jj = j0 + tx + 16*j;
            C[(size_t)m * 512 + jj] = acc[i][j] + bias[jj];
        }
    }
}

// ---------------------------------------------------------------------------
// Main fused kernel, fp16 m16n8k16 mma.sync:
//   out[row][v] = sum_k tanh(encP[..][k] + decP[..][k]) * Wout[v][k] + bout[v]
//
// CTA tile 128 rows x 256 vocab, BK=32 (2 ksteps of 16), grid (2, 625).
// 8 warps: warpM=wid&1 (64 rows) x warpN=wid>>1 (64 cols) = 4x8 atoms, acc 128.
//
// Smem (static, 48KB exactly, double-buffered):
//   A_s[2][matom 8][ksl 2][lane 32] uint4  (8KB/buf)
//     lane (g=l>>2,t=l&3): {h2(act[16m+g][kb+2t..]), h2(act[16m+8+g][..]),
//                           h2(act[16m+g][kb+2t+8..]), h2(act[16m+8+g][..])}
//   B_s[2][natom 32][ksl 2][lane 32] uint2 (16KB/buf) -- copied via cp.async
//     straight from the pre-packed g_Bh (fragment order already).
// ---------------------------------------------------------------------------
__global__ __launch_bounds__(256, 1) void joiner_hmma(
    const float* __restrict__ bout,   // [500]
    float* __restrict__ out)          // [80000][500]
{
    __shared__ __align__(16) uint32_t A_s[2 * 2048];   // 16 KB
    __shared__ __align__(16) uint32_t B_s[2 * 4096];   // 32 KB

    const int tid  = threadIdx.x;
    const int wid  = tid >> 5;
    const int lane = tid & 31;
    const long r0  = (long)blockIdx.y * 128;
    const int vt   = blockIdx.x;               // 0..1
    const int v0   = vt * 256;
    const int warpM = wid & 1;
    const int warpN = wid >> 1;

    // ---- A staging identity: matom = wid, g = (tid>>2)&7, t = tid&3 ----
    const int sa_m = tid >> 5;
    const int sa_g = (tid >> 2) & 7;
    const int sa_t = tid & 3;
    const long rowA0 = r0 + sa_m * 16 + sa_g;
    const long rowA1 = rowA0 + 8;
    const int nt0 = (int)(rowA0 / U_);
    const int u0  = (int)(rowA0 - (long)nt0 * U_);
    const int nt1 = (int)(rowA1 / U_);
    const int u1  = (int)(rowA1 - (long)nt1 * U_);
    const float* encR0 = g_encP + (size_t)nt0 * J_;
    const float* decR0 = g_decP + ((size_t)(nt0 / T_) * U_ + u0) * J_;
    const float* encR1 = g_encP + (size_t)nt1 * J_;
    const float* decR1 = g_decP + ((size_t)(nt1 / T_) * U_ + u1) * J_;
    // A_s u32 index for (ksl): ((sa_m*2+ksl)*32 + lane)*4, lane = tid&31
    const int a_idx0 = ((sa_m * 2 + 0) * 32 + (tid & 31)) * 4;

    // ---- B cp.async identity ----
    const int b_lp  = tid & 15;          // lane-pair (16B = 2 lanes)
    const int b_ksl = (tid >> 4) & 1;
    const int b_na0 = tid >> 5;          // + 8*q, q=0..3
    const char* bh_base = (const char*)g_Bh;
    const uint32_t smemB = smem_u32(B_s);

    float acc[4][8][4];
#pragma unroll
    for (int i = 0; i < 4; i++)
#pragma unroll
        for (int j = 0; j < 8; j++)
#pragma unroll
            for (int c = 0; c < 4; c++) acc[i][j][c] = 0.f;

    // ---- B async copy: chunk kc -> buffer buf ----
    auto copyB = [&](int kc, int buf) {
#pragma unroll
        for (int q = 0; q < 4; q++) {
            const int na = b_na0 + 8 * q;
            const long goff = (long)((vt * 32 + na) * 32 + 2 * kc + b_ksl) * 256
                              + b_lp * 16;
            const uint32_t soff = (uint32_t)buf * 16384u
                                  + (uint32_t)((na * 2 + b_ksl) * 256 + b_lp * 16);
            asm volatile("cp.async.cg.shared.global [%0], [%1], 16;"
                         :: "r"(smemB + soff), "l"(bh_base + goff));
        }
        asm volatile("cp.async.commit_group;" ::: "memory");
    };
    // ---- A load (gmem -> regs) for chunk kc ----
    float2 e0[2][2], e1[2][2], d0[2][2], d1[2][2];  // [ksl][lo/hi-8]
    auto loadA = [&](int kc) {
#pragma unroll
        for (int ksl = 0; ksl < 2; ksl++) {
            const int kb = kc * 32 + ksl * 16 + 2 * sa_t;
            e0[ksl][0] = *(const float2*)(encR0 + kb);
            e0[ksl][1] = *(const float2*)(encR0 + kb + 8);
            e1[ksl][0] = *(const float2*)(encR1 + kb);
            e1[ksl][1] = *(const float2*)(encR1 + kb + 8);
            d0[ksl][0] = *(const float2*)(decR0 + kb);
            d0[ksl][1] = *(const float2*)(decR0 + kb + 8);
            d1[ksl][0] = *(const float2*)(decR1 + kb);
            d1[ksl][1] = *(const float2*)(decR1 + kb + 8);
        }
    };
    // ---- A math + store (regs -> smem buf) ----
    auto mathA = [&](int buf) {
        uint32_t* base = A_s + buf * 2048 + a_idx0;
#pragma unroll
        for (int ksl = 0; ksl < 2; ksl++) {
            uint4 w4;
            w4.x = h2u(atanh_(e0[ksl][0].x + d0[ksl][0].x),
                       atanh_(e0[ksl][0].y + d0[ksl][0].y));
            w4.y = h2u(atanh_(e1[ksl][0].x + d1[ksl][0].x),
                       atanh_(e1[ksl][0].y + d1[ksl][0].y));
            w4.z = h2u(atanh_(e0[ksl][1].x + d0[ksl][1].x),
                       atanh_(e0[ksl][1].y + d0[ksl][1].y));
            w4.w = h2u(atanh_(e1[ksl][1].x + d1[ksl][1].x),
                       atanh_(e1[ksl][1].y + d1[ksl][1].y));
            *(uint4*)(base + ksl * 128) = w4;      // (+1 ksl) -> +32 lanes*4 u32
        }
    };

    // -------- prologue: chunk 0 into buffer 0 --------
    copyB(0, 0);
    loadA(0);
    mathA(0);
    asm volatile("cp.async.wait_group 0;" ::: "memory");
    __syncthreads();

    // -------- main loop: 16 chunks, double-buffered --------
#pragma unroll 1
    for (int kc = 0; kc < 16; kc++) {
        const int cur = kc & 1;

        if (kc < 15) {
            copyB(kc + 1, 1 - cur);    // async, in flight under consume
            loadA(kc + 1);             // LDGs issued, consumed after the MMAs
        }

        // consume current buffer: 2 ksteps of m16n8k16
        const uint32_t* Ab = A_s + cur * 2048;
        const uint32_t* Bb = B_s + cur * 4096;
#pragma unroll
        for (int ksl = 0; ksl < 2; ksl++) {
            uint32_t af[4][4];
            uint32_t bf[8][2];
#pragma unroll
            for (int i = 0; i < 4; i++) {
                const uint4 va = *(const uint4*)
                    (Ab + (((warpM * 4 + i) * 2 + ksl) * 32 + lane) * 4);
                af[i][0] = va.x; af[i][1] = va.y; af[i][2] = va.z; af[i][3] = va.w;
            }
#pragma unroll
            for (int j = 0; j < 8; j++) {
                const uint2 vb = *(const uint2*)
                    (Bb + (((warpN * 8 + j) * 2 + ksl) * 32 + lane) * 2);
                bf[j][0] = vb.x; bf[j][1] = vb.y;
            }
#pragma unroll
            for (int i = 0; i < 4; i++)
#pragma unroll
                for (int j = 0; j < 8; j++) {
                    asm volatile(
                        "mma.sync.aligned.m16n8k16.row.col.f32.f16.f16.f32 "
                        "{%0,%1,%2,%3}, {%4,%5,%6,%7}, {%8,%9}, {%0,%1,%2,%3};"
                        : "+f"(acc[i][j][0]), "+f"(acc[i][j][1]),
                          "+f"(acc[i][j][2]), "+f"(acc[i][j][3])
                        : "r"(af[i][0]), "r"(af[i][1]), "r"(af[i][2]), "r"(af[i][3]),
                          "r"(bf[j][0]), "r"(bf[j][1]));
                }
        }

        if (kc < 15) mathA(1 - cur);   // tanh + pack + STS for next chunk
        asm volatile("cp.async.wait_group 0;" ::: "memory");
        __syncthreads();
    }

    // -------- epilogue: registers -> gmem, +bias, float2 stores --------
    const int cpair = (lane & 3) * 2;
    const int rsub  = lane >> 2;
#pragma unroll
    for (int j = 0; j < 8; j++) {
        const int col = v0 + warpN * 64 + j * 8 + cpair;
        if (col >= V_) continue;                  // V_ even: pair never straddles
        const float2 bb = *(const float2*)(bout + col);
#pragma unroll
        for (int i = 0; i < 4; i++) {
            const long rr = r0 + warpM * 64 + i * 16 + rsub;
            float2 o0, o1;
            o0.x = acc[i][j][0] + bb.x;
            o0.y = acc[i][j][1] + bb.y;
            o1.x = acc[i][j][2] + bb.x;
            o1.y = acc[i][j][3] + bb.y;
            *(float2*)(out + rr * (long)V_ + col)       = o0;
            *(float2*)(out + (rr + 8) * (long)V_ + col) = o1;
        }
    }
}

// ---------------------------------------------------------------------------
extern "C" void kernel_launch(void* const* d_in, const int* in_sizes, int n_in,
                              void* d_out, int out_size)
{
    (void)in_sizes; (void)n_in; (void)out_size;
    const float* encoder_out = (const float*)d_in[0];  // [8,200,512]
    const float* decoder_out = (const float*)d_in[1];  // [8,50,512]
    const float* W_enc       = (const float*)d_in[2];  // [512,512]
    const float* b_enc       = (const float*)d_in[3];  // [512]
    const float* W_dec       = (const float*)d_in[4];  // [512,512]
    const float* b_dec       = (const float*)d_in[5];  // [512]
    const float* W_out       = (const float*)d_in[6];  // [500,512]
    const float* b_out       = (const float*)d_in[7];  // [500]
    float* out = (float*)d_out;                        // [8,200,50,500]

    float* encP = nullptr;
    float* decP = nullptr;
    cudaGetSymbolAddress((void**)&encP, g_encP);
    cudaGetSymbolAddress((void**)&decP, g_decP);

    // pack W_out to fp16 fragment order (independent of projections)
    pack_w<<<256, 256>>>(W_out);

    // merged projections (enc: 25 y-tiles, dec: 7 y-tiles)
    {
        dim3 grid(8, 32);
        proj_both<<<grid, 256>>>(encoder_out, W_enc, b_enc, encP,
                                 decoder_out, W_dec, b_dec, decP);
    }
    // main fused tanh + fp16 mma.sync GEMM
    {
        dim3 grid(2, 625);   // N-tiles x M-tiles
        joiner_hmma<<<grid, 256>>>(b_out, out);
    }
}